// round 1
// baseline (speedup 1.0000x reference)
#include <cuda_runtime.h>
#include <cuda_bf16.h>
#include <cstdint>

#define BB 256
#define NN 256
#define MM 256
#define DD 1024
#define RBAND 128
#define BIGF 1e30f

// Scratch (static __device__ per allocation rules)
__device__ __nv_bfloat16 g_s1n[(size_t)BB * NN * DD];         // normalized seq1, bf16
__device__ __nv_bfloat16 g_s2n[(size_t)BB * MM * DD];         // normalized seq2, bf16
__device__ float g_distD[(size_t)BB * 512 * 256];             // dist in diagonal layout [b][i+j][j]

// ---------------------------------------------------------------------------
// Kernel 1: L2-normalize each length-1024 row, convert to bf16.
// One warp per row; lane holds 8 float4 (32 elems).
// ---------------------------------------------------------------------------
__global__ void norm_kernel(const float* __restrict__ s1, const float* __restrict__ s2) {
    int wg   = (blockIdx.x * blockDim.x + threadIdx.x) >> 5;
    int lane = threadIdx.x & 31;
    const float* src;
    __nv_bfloat16* dst;
    if (wg < BB * NN) {
        src = s1 + (size_t)wg * DD;
        dst = g_s1n + (size_t)wg * DD;
    } else {
        int r = wg - BB * NN;
        src = s2 + (size_t)r * DD;
        dst = g_s2n + (size_t)r * DD;
    }
    float4 v[8];
    float ss = 0.f;
#pragma unroll
    for (int c = 0; c < 8; c++) {
        v[c] = *(const float4*)(src + c * 128 + lane * 4);
        ss += v[c].x * v[c].x + v[c].y * v[c].y + v[c].z * v[c].z + v[c].w * v[c].w;
    }
#pragma unroll
    for (int o = 16; o > 0; o >>= 1) ss += __shfl_xor_sync(0xffffffffu, ss, o);
    float inv = 1.0f / fmaxf(sqrtf(ss), 1e-12f);
#pragma unroll
    for (int c = 0; c < 8; c++) {
        __nv_bfloat162 p0 = __floats2bfloat162_rn(v[c].x * inv, v[c].y * inv);
        __nv_bfloat162 p1 = __floats2bfloat162_rn(v[c].z * inv, v[c].w * inv);
        uint2 w;
        w.x = *reinterpret_cast<unsigned int*>(&p0);
        w.y = *reinterpret_cast<unsigned int*>(&p1);
        *(uint2*)(dst + c * 128 + lane * 4) = w;
    }
}

// ---------------------------------------------------------------------------
// Kernel 2: batched GEMM sim = A @ B^T (both K-major), bf16 mma.sync, fp32 acc.
// Grid (2,2,B): 128x128 tile per CTA, 256 threads = 8 warps (2 along M, 4 along N),
// warp tile 64x32. K-tile 32, double-buffered smem, pad stride 40 (conflict-free
// fragment reads). Epilogue: dist = 1 - clamp(sim,-1,1) written in DIAGONAL layout.
// ---------------------------------------------------------------------------
#define KT 32
#define LDP 40

__global__ __launch_bounds__(256, 2) void gemm_kernel() {
    __shared__ __nv_bfloat16 As[2][128 * LDP];
    __shared__ __nv_bfloat16 Bs[2][128 * LDP];

    int b  = blockIdx.z;
    int i0 = blockIdx.x * 128;
    int j0 = blockIdx.y * 128;
    int t    = threadIdx.x;
    int lane = t & 31;
    int w    = t >> 5;
    int wm = w & 1;        // 0..1  (M)
    int wn = w >> 1;       // 0..3  (N)
    int gid = lane >> 2;   // 0..7
    int tig = lane & 3;    // 0..3

    const __nv_bfloat16* Ag = g_s1n + (size_t)b * NN * DD + (size_t)i0 * DD;
    const __nv_bfloat16* Bg = g_s2n + (size_t)b * MM * DD + (size_t)j0 * DD;

    int lr = t >> 3;        // 0..31 (row within 32-row group)
    int lc = (t & 7) * 4;   // k-col 0,4,...,28

    float acc[4][4][4];
#pragma unroll
    for (int mt = 0; mt < 4; mt++)
#pragma unroll
        for (int nt = 0; nt < 4; nt++)
#pragma unroll
            for (int c = 0; c < 4; c++) acc[mt][nt][c] = 0.f;

    uint2 ra[4], rb[4];
#pragma unroll
    for (int r4 = 0; r4 < 4; r4++) {
        ra[r4] = *(const uint2*)(Ag + (size_t)(lr + r4 * 32) * DD + lc);
        rb[r4] = *(const uint2*)(Bg + (size_t)(lr + r4 * 32) * DD + lc);
    }
    int buf = 0;
#pragma unroll
    for (int r4 = 0; r4 < 4; r4++) {
        *(uint2*)&As[buf][(lr + r4 * 32) * LDP + lc] = ra[r4];
        *(uint2*)&Bs[buf][(lr + r4 * 32) * LDP + lc] = rb[r4];
    }
    __syncthreads();

    for (int kt = 0; kt < DD / KT; kt++) {
        int nk = kt + 1;
        if (nk < DD / KT) {
#pragma unroll
            for (int r4 = 0; r4 < 4; r4++) {
                ra[r4] = *(const uint2*)(Ag + (size_t)(lr + r4 * 32) * DD + nk * KT + lc);
                rb[r4] = *(const uint2*)(Bg + (size_t)(lr + r4 * 32) * DD + nk * KT + lc);
            }
        }
#pragma unroll
        for (int kk = 0; kk < KT; kk += 16) {
            uint32_t af[4][4];
            uint32_t bf[4][2];
#pragma unroll
            for (int mt = 0; mt < 4; mt++) {
                int row  = wm * 64 + mt * 16 + gid;
                int base = row * LDP + kk + tig * 2;
                af[mt][0] = *(const uint32_t*)&As[buf][base];
                af[mt][1] = *(const uint32_t*)&As[buf][base + 8 * LDP];
                af[mt][2] = *(const uint32_t*)&As[buf][base + 8];
                af[mt][3] = *(const uint32_t*)&As[buf][base + 8 * LDP + 8];
            }
#pragma unroll
            for (int nt = 0; nt < 4; nt++) {
                int col  = wn * 32 + nt * 8 + gid;
                int base = col * LDP + kk + tig * 2;
                bf[nt][0] = *(const uint32_t*)&Bs[buf][base];
                bf[nt][1] = *(const uint32_t*)&Bs[buf][base + 8];
            }
#pragma unroll
            for (int mt = 0; mt < 4; mt++)
#pragma unroll
                for (int nt = 0; nt < 4; nt++) {
                    asm volatile(
                        "mma.sync.aligned.m16n8k16.row.col.f32.bf16.bf16.f32 "
                        "{%0,%1,%2,%3}, {%4,%5,%6,%7}, {%8,%9}, {%0,%1,%2,%3};\n"
                        : "+f"(acc[mt][nt][0]), "+f"(acc[mt][nt][1]),
                          "+f"(acc[mt][nt][2]), "+f"(acc[mt][nt][3])
                        : "r"(af[mt][0]), "r"(af[mt][1]), "r"(af[mt][2]), "r"(af[mt][3]),
                          "r"(bf[nt][0]), "r"(bf[nt][1]));
                }
        }
        if (nk < DD / KT) {
            int nbuf = buf ^ 1;
#pragma unroll
            for (int r4 = 0; r4 < 4; r4++) {
                *(uint2*)&As[nbuf][(lr + r4 * 32) * LDP + lc] = ra[r4];
                *(uint2*)&Bs[nbuf][(lr + r4 * 32) * LDP + lc] = rb[r4];
            }
        }
        __syncthreads();
        buf ^= 1;
    }

    // Epilogue: dist = 1 - clamp(sim), scattered into diagonal layout.
    float* dd = g_distD + (size_t)b * 512 * 256;
#pragma unroll
    for (int mt = 0; mt < 4; mt++) {
#pragma unroll
        for (int nt = 0; nt < 4; nt++) {
            int ib = i0 + wm * 64 + mt * 16 + gid;
            int jb = j0 + wn * 32 + nt * 8 + tig * 2;
#pragma unroll
            for (int c = 0; c < 4; c++) {
                int i = ib + ((c >= 2) ? 8 : 0);
                int j = jb + (c & 1);
                float sim = fminf(fmaxf(acc[mt][nt][c], -1.f), 1.f);
                dd[(i + j) * 256 + j] = 1.0f - sim;
            }
        }
    }
}

// ---------------------------------------------------------------------------
// Kernel 3: banded DTW, anti-diagonal wavefront. One warp per batch; lane owns
// columns [8*lane, 8*lane+7] in registers; previous two diagonals in registers;
// left-neighbor crossing lane boundary via shfl.up. Distance rows streamed with
// an 8-deep cp.async ring (each lane copies exactly its own 32B).
// ---------------------------------------------------------------------------
#define SDEPTH 8

__global__ __launch_bounds__(128) void dtw_kernel(float* __restrict__ out) {
    __shared__ float ring[4][SDEPTH][256];
    int w     = threadIdx.x >> 5;
    int lane  = threadIdx.x & 31;
    int batch = blockIdx.x * 4 + w;
    const float* dd = g_distD + (size_t)batch * 512 * 256;

    // prologue: issue rows 0..SDEPTH-1
    for (int s = 0; s < SDEPTH; s++) {
        uint32_t sa = (uint32_t)__cvta_generic_to_shared(&ring[w][s][lane * 8]);
        const float* src = dd + (size_t)s * 256 + lane * 8;
        asm volatile("cp.async.cg.shared.global [%0], [%1], 16;\n" ::"r"(sa), "l"(src) : "memory");
        asm volatile("cp.async.cg.shared.global [%0], [%1], 16;\n" ::"r"(sa + 16), "l"(src + 4) : "memory");
        asm volatile("cp.async.commit_group;\n" ::: "memory");
    }

    float d1[8], d2[8];
#pragma unroll
    for (int u = 0; u < 8; u++) { d1[u] = BIGF; d2[u] = BIGF; }

    int jbase = lane * 8;
    for (int k = 0; k < 511; k++) {
        asm volatile("cp.async.wait_group 7;\n" ::: "memory");
        float cur[8];
        const float* slot = &ring[w][k & (SDEPTH - 1)][jbase];
#pragma unroll
        for (int u = 0; u < 8; u++) cur[u] = slot[u];

        // issue row k+SDEPTH into the slot we just drained
        {
            int nk = k + SDEPTH;
            if (nk < 512) {
                uint32_t sa = (uint32_t)__cvta_generic_to_shared(&ring[w][nk & (SDEPTH - 1)][lane * 8]);
                const float* src = dd + (size_t)nk * 256 + lane * 8;
                asm volatile("cp.async.cg.shared.global [%0], [%1], 16;\n" ::"r"(sa), "l"(src) : "memory");
                asm volatile("cp.async.cg.shared.global [%0], [%1], 16;\n" ::"r"(sa + 16), "l"(src + 4) : "memory");
            }
            asm volatile("cp.async.commit_group;\n" ::: "memory");
        }

        float pl1 = __shfl_up_sync(0xffffffffu, d1[7], 1);
        float pl2 = __shfl_up_sync(0xffffffffu, d2[7], 1);

        float nv[8];
#pragma unroll
        for (int u = 0; u < 8; u++) {
            int j = jbase + u;
            int i = k - j;
            float d  = cur[u];
            float lf = u ? d1[u - 1] : pl1;
            float ul = u ? d2[u - 1] : pl2;
            float up = d1[u];
            float v;
            if (i == 0) {
                v = (j == 0) ? d : ((j <= RBAND) ? lf + d : BIGF);
            } else if (j == 0) {
                v = (i >= 1 && i <= RBAND) ? up + d : BIGF;
            } else {
                bool act = (i >= 1) && (i <= 255) && (j >= i - RBAND) && (j <= i + RBAND);
                v = act ? fminf(fminf(up, lf), ul) + d : BIGF;
            }
            nv[u] = v;
        }
#pragma unroll
        for (int u = 0; u < 8; u++) { d2[u] = d1[u]; d1[u] = nv[u]; }
    }

    if (lane == 31) out[batch] = d1[7];  // cell (255,255) on diagonal 510
}

// ---------------------------------------------------------------------------
extern "C" void kernel_launch(void* const* d_in, const int* in_sizes, int n_in,
                              void* d_out, int out_size) {
    const float* s1 = (const float*)d_in[0];
    const float* s2 = (const float*)d_in[1];
    float* out = (float*)d_out;

    // 131072 rows total, 8 warps (256 thr) per block
    norm_kernel<<<(BB * NN + BB * MM) / 8, 256>>>(s1, s2);

    dim3 g(2, 2, BB);
    gemm_kernel<<<g, 256>>>();

    dtw_kernel<<<64, 128>>>(out);
}

// round 3
// speedup vs baseline: 1.6101x; 1.6101x over previous
#include <cuda_runtime.h>
#include <cuda_bf16.h>
#include <cstdint>

#define BB 256
#define NN 256
#define MM 256
#define DD 1024
#define RBAND 128
#define BIGF 1e30f

// Scratch (static __device__ per allocation rules)
__device__ __nv_bfloat16 g_s1n[(size_t)BB * NN * DD];   // normalized seq1, bf16
__device__ __nv_bfloat16 g_s2n[(size_t)BB * MM * DD];   // normalized seq2, bf16
__device__ float g_dist[(size_t)BB * 256 * 256];        // dist row-major [b][i][j]

static __device__ __forceinline__ uint32_t smem_u32(const void* p) {
    uint32_t a;
    asm("{ .reg .u64 t; cvta.to.shared.u64 t, %1; cvt.u32.u64 %0, t; }" : "=r"(a) : "l"(p));
    return a;
}
static __device__ __forceinline__ void cp16(uint32_t dst, const void* src) {
    asm volatile("cp.async.cg.shared.global [%0], [%1], 16;\n" ::"r"(dst), "l"(src) : "memory");
}
static __device__ __forceinline__ void ldsm_x4(uint32_t& r0, uint32_t& r1, uint32_t& r2,
                                               uint32_t& r3, uint32_t addr) {
    asm volatile("ldmatrix.sync.aligned.m8n8.x4.shared.b16 {%0,%1,%2,%3}, [%4];"
                 : "=r"(r0), "=r"(r1), "=r"(r2), "=r"(r3) : "r"(addr));
}

// ---------------------------------------------------------------------------
// Kernel 1: L2-normalize each length-1024 row, convert to bf16.
// ---------------------------------------------------------------------------
__global__ void norm_kernel(const float* __restrict__ s1, const float* __restrict__ s2) {
    int wg   = (blockIdx.x * blockDim.x + threadIdx.x) >> 5;
    int lane = threadIdx.x & 31;
    const float* src;
    __nv_bfloat16* dst;
    if (wg < BB * NN) {
        src = s1 + (size_t)wg * DD;
        dst = g_s1n + (size_t)wg * DD;
    } else {
        int r = wg - BB * NN;
        src = s2 + (size_t)r * DD;
        dst = g_s2n + (size_t)r * DD;
    }
    float4 v[8];
    float ss = 0.f;
#pragma unroll
    for (int c = 0; c < 8; c++) {
        v[c] = *(const float4*)(src + c * 128 + lane * 4);
        ss += v[c].x * v[c].x + v[c].y * v[c].y + v[c].z * v[c].z + v[c].w * v[c].w;
    }
#pragma unroll
    for (int o = 16; o > 0; o >>= 1) ss += __shfl_xor_sync(0xffffffffu, ss, o);
    float inv = 1.0f / fmaxf(sqrtf(ss), 1e-12f);
#pragma unroll
    for (int c = 0; c < 8; c++) {
        __nv_bfloat162 p0 = __floats2bfloat162_rn(v[c].x * inv, v[c].y * inv);
        __nv_bfloat162 p1 = __floats2bfloat162_rn(v[c].z * inv, v[c].w * inv);
        uint2 w;
        w.x = *reinterpret_cast<unsigned int*>(&p0);
        w.y = *reinterpret_cast<unsigned int*>(&p1);
        *(uint2*)(dst + c * 128 + lane * 4) = w;
    }
}

// ---------------------------------------------------------------------------
// Kernel 2: batched GEMM sim = A @ B^T, bf16 mma.sync + ldmatrix fragments.
// Grid (2,2,B), 128x128 tile per CTA, 256 thr (8 warps: 2 M x 4 N), warp tile
// 64x32, K-tile 32, double-buffered smem pad-40. Epilogue: dist=1-clamp(sim)
// stored ROW-MAJOR as float2 (coalesced 32B sectors).
// ---------------------------------------------------------------------------
#define KT 32
#define LDP 40

__global__ __launch_bounds__(256, 2) void gemm_kernel() {
    __shared__ __nv_bfloat16 As[2][128 * LDP];
    __shared__ __nv_bfloat16 Bs[2][128 * LDP];

    int b  = blockIdx.z;
    int i0 = blockIdx.x * 128;
    int j0 = blockIdx.y * 128;
    int t    = threadIdx.x;
    int lane = t & 31;
    int w    = t >> 5;
    int wm = w & 1;
    int wn = w >> 1;
    int gid = lane >> 2;
    int tig = lane & 3;

    const __nv_bfloat16* Ag = g_s1n + (size_t)b * NN * DD + (size_t)i0 * DD;
    const __nv_bfloat16* Bg = g_s2n + (size_t)b * MM * DD + (size_t)j0 * DD;

    int lr = t >> 3;        // 0..31
    int lc = (t & 7) * 4;   // 0..28

    float acc[4][4][4];
#pragma unroll
    for (int mt = 0; mt < 4; mt++)
#pragma unroll
        for (int nt = 0; nt < 4; nt++)
#pragma unroll
            for (int c = 0; c < 4; c++) acc[mt][nt][c] = 0.f;

    uint2 ra[4], rb[4];
#pragma unroll
    for (int r4 = 0; r4 < 4; r4++) {
        ra[r4] = *(const uint2*)(Ag + (size_t)(lr + r4 * 32) * DD + lc);
        rb[r4] = *(const uint2*)(Bg + (size_t)(lr + r4 * 32) * DD + lc);
    }
    int buf = 0;
#pragma unroll
    for (int r4 = 0; r4 < 4; r4++) {
        *(uint2*)&As[buf][(lr + r4 * 32) * LDP + lc] = ra[r4];
        *(uint2*)&Bs[buf][(lr + r4 * 32) * LDP + lc] = rb[r4];
    }
    __syncthreads();

    // ldmatrix lane address components (constant across k-loop)
    int a_row_in = (lane & 15);          // row within 16-row A tile
    int a_koff   = (lane >> 4) * 8;      // 0 or 8 (k halves)
    int b_row_in = ((lane >> 4) << 3) + (lane & 7);  // row within 16-row B tile
    int b_koff   = ((lane >> 3) & 1) * 8;            // 0 or 8

    for (int kt = 0; kt < DD / KT; kt++) {
        int nk = kt + 1;
        if (nk < DD / KT) {
#pragma unroll
            for (int r4 = 0; r4 < 4; r4++) {
                ra[r4] = *(const uint2*)(Ag + (size_t)(lr + r4 * 32) * DD + nk * KT + lc);
                rb[r4] = *(const uint2*)(Bg + (size_t)(lr + r4 * 32) * DD + nk * KT + lc);
            }
        }
#pragma unroll
        for (int kk = 0; kk < KT; kk += 16) {
            uint32_t af[4][4];
            uint32_t bf2[2][4];
#pragma unroll
            for (int mt = 0; mt < 4; mt++) {
                int arow = wm * 64 + mt * 16 + a_row_in;
                uint32_t addr = smem_u32(&As[buf][arow * LDP + kk + a_koff]);
                ldsm_x4(af[mt][0], af[mt][1], af[mt][2], af[mt][3], addr);
            }
#pragma unroll
            for (int ntp = 0; ntp < 2; ntp++) {
                int brow = wn * 32 + ntp * 16 + b_row_in;
                uint32_t addr = smem_u32(&Bs[buf][brow * LDP + kk + b_koff]);
                ldsm_x4(bf2[ntp][0], bf2[ntp][1], bf2[ntp][2], bf2[ntp][3], addr);
            }
#pragma unroll
            for (int mt = 0; mt < 4; mt++)
#pragma unroll
                for (int nt = 0; nt < 4; nt++) {
                    uint32_t b0 = bf2[nt >> 1][(nt & 1) * 2];
                    uint32_t b1 = bf2[nt >> 1][(nt & 1) * 2 + 1];
                    asm volatile(
                        "mma.sync.aligned.m16n8k16.row.col.f32.bf16.bf16.f32 "
                        "{%0,%1,%2,%3}, {%4,%5,%6,%7}, {%8,%9}, {%0,%1,%2,%3};\n"
                        : "+f"(acc[mt][nt][0]), "+f"(acc[mt][nt][1]),
                          "+f"(acc[mt][nt][2]), "+f"(acc[mt][nt][3])
                        : "r"(af[mt][0]), "r"(af[mt][1]), "r"(af[mt][2]), "r"(af[mt][3]),
                          "r"(b0), "r"(b1));
                }
        }
        if (nk < DD / KT) {
            int nbuf = buf ^ 1;
#pragma unroll
            for (int r4 = 0; r4 < 4; r4++) {
                *(uint2*)&As[nbuf][(lr + r4 * 32) * LDP + lc] = ra[r4];
                *(uint2*)&Bs[nbuf][(lr + r4 * 32) * LDP + lc] = rb[r4];
            }
        }
        __syncthreads();
        buf ^= 1;
    }

    // Epilogue: dist = 1 - clamp(sim), ROW-MAJOR float2 stores (coalesced).
    float* dT = g_dist + (size_t)b * 65536;
#pragma unroll
    for (int mt = 0; mt < 4; mt++) {
#pragma unroll
        for (int nt = 0; nt < 4; nt++) {
            int i = i0 + wm * 64 + mt * 16 + gid;
            int j = j0 + wn * 32 + nt * 8 + tig * 2;
            float2 v0, v1;
            v0.x = 1.0f - fminf(fmaxf(acc[mt][nt][0], -1.f), 1.f);
            v0.y = 1.0f - fminf(fmaxf(acc[mt][nt][1], -1.f), 1.f);
            v1.x = 1.0f - fminf(fmaxf(acc[mt][nt][2], -1.f), 1.f);
            v1.y = 1.0f - fminf(fmaxf(acc[mt][nt][3], -1.f), 1.f);
            *(float2*)&dT[(size_t)i * 256 + j]       = v0;
            *(float2*)&dT[(size_t)(i + 8) * 256 + j] = v1;
        }
    }
}

// ---------------------------------------------------------------------------
// Kernel 3: banded DTW, row-streaming min-plus scan (the reference recurrence
// solved with serial-in-lane + warp (min,+) scan). One warp per batch; lane
// owns 8 columns. Rows prefetched via cp.async ring.
// ---------------------------------------------------------------------------
#define SDEPTH 8

__global__ __launch_bounds__(128) void dtw_kernel(float* __restrict__ out) {
    __shared__ float ring[4][SDEPTH][256];
    int w     = threadIdx.x >> 5;
    int lane  = threadIdx.x & 31;
    int batch = blockIdx.x * 4 + w;
    const float* E = g_dist + (size_t)batch * 65536;
    int cbase = lane * 8;

    for (int s = 0; s < SDEPTH; s++) {
        uint32_t sa = smem_u32(&ring[w][s][cbase]);
        const float* src = E + (size_t)s * 256 + cbase;
        cp16(sa, src);
        cp16(sa + 16, src + 4);
        asm volatile("cp.async.commit_group;\n" ::: "memory");
    }

    float prev[8];

    for (int r = 0; r < 256; r++) {
        asm volatile("cp.async.wait_group 7;\n" ::: "memory");
        float e[8];
        const float* slot = &ring[w][r & (SDEPTH - 1)][cbase];
#pragma unroll
        for (int u = 0; u < 8; u++) e[u] = slot[u];

        int nr = r + SDEPTH;
        if (nr < 256) {
            uint32_t sa = smem_u32(&ring[w][nr & (SDEPTH - 1)][cbase]);
            const float* src = E + (size_t)nr * 256 + cbase;
            cp16(sa, src);
            cp16(sa + 16, src + 4);
        }
        asm volatile("cp.async.commit_group;\n" ::: "memory");

        if (r == 0) {
            float ps[8];
            float run = 0.f;
#pragma unroll
            for (int u = 0; u < 8; u++) { run += e[u]; ps[u] = run; }
            float acc = run;
#pragma unroll
            for (int d = 1; d < 32; d <<= 1) {
                float p = __shfl_up_sync(0xffffffffu, acc, d);
                if (lane >= d) acc += p;
            }
            float excl = acc - run;
#pragma unroll
            for (int u = 0; u < 8; u++) {
                float tv = excl + ps[u];
                prev[u] = (cbase + u <= RBAND) ? tv : BIGF;
            }
        } else {
            float pl = __shfl_up_sync(0xffffffffu, prev[7], 1);
            if (lane == 0) pl = BIGF;
            float bb[8], ss[8];
#pragma unroll
            for (int u = 0; u < 8; u++) {
                int c = cbase + u;
                float pjm1 = u ? prev[u - 1] : pl;
                bool ib = (c >= 1) && (c >= r - RBAND) && (c <= r + RBAND);
                bb[u] = ib ? fminf(prev[u], pjm1) + e[u] : BIGF;
                ss[u] = ib ? e[u] : BIGF;
            }
            if (lane == 0) {
                bb[0] = (r <= RBAND) ? prev[0] + e[0] : BIGF;
                ss[0] = BIGF;
            }
            float tl[8], P[8];
            tl[0] = bb[0];
            P[0]  = ss[0];
#pragma unroll
            for (int u = 1; u < 8; u++) {
                tl[u] = fminf(bb[u], tl[u - 1] + ss[u]);
                P[u]  = P[u - 1] + ss[u];
            }
            float S = P[7], T = tl[7];
#pragma unroll
            for (int d = 1; d < 32; d <<= 1) {
                float Sp = __shfl_up_sync(0xffffffffu, S, d);
                float Tp = __shfl_up_sync(0xffffffffu, T, d);
                if (lane >= d) {
                    T = fminf(T, Tp + S);
                    S = S + Sp;
                }
            }
            float cin = __shfl_up_sync(0xffffffffu, T, 1);
            if (lane == 0) cin = BIGF;
#pragma unroll
            for (int u = 0; u < 8; u++) prev[u] = fminf(tl[u], cin + P[u]);
        }
    }

    if (lane == 31) out[batch] = prev[7];
}

// ---------------------------------------------------------------------------
extern "C" void kernel_launch(void* const* d_in, const int* in_sizes, int n_in,
                              void* d_out, int out_size) {
    const float* s1 = (const float*)d_in[0];
    const float* s2 = (const float*)d_in[1];
    float* out = (float*)d_out;

    norm_kernel<<<(BB * NN + BB * MM) / 8, 256>>>(s1, s2);

    dim3 g(2, 2, BB);
    gemm_kernel<<<g, 256>>>();

    dtw_kernel<<<64, 128>>>(out);
}

// round 4
// speedup vs baseline: 1.9189x; 1.1918x over previous
#include <cuda_runtime.h>
#include <cuda_bf16.h>
#include <cstdint>

#define BB 256
#define NN 256
#define MM 256
#define DD 1024
#define RBAND 128
#define BIGF 1e30f

// Scratch (static __device__ per allocation rules)
__device__ float g_dist[(size_t)BB * 256 * 256];        // dist row-major [b][i][j]

static __device__ __forceinline__ uint32_t smem_u32(const void* p) {
    uint32_t a;
    asm("{ .reg .u64 t; cvta.to.shared.u64 t, %1; cvt.u32.u64 %0, t; }" : "=r"(a) : "l"(p));
    return a;
}
static __device__ __forceinline__ void cp16(uint32_t dst, const void* src) {
    asm volatile("cp.async.cg.shared.global [%0], [%1], 16;\n" ::"r"(dst), "l"(src) : "memory");
}
static __device__ __forceinline__ void ldsm_x4(uint32_t& r0, uint32_t& r1, uint32_t& r2,
                                               uint32_t& r3, uint32_t addr) {
    asm volatile("ldmatrix.sync.aligned.m8n8.x4.shared.b16 {%0,%1,%2,%3}, [%4];"
                 : "=r"(r0), "=r"(r1), "=r"(r2), "=r"(r3) : "r"(addr));
}
static __device__ __forceinline__ uint2 cvt_f4_bf16(float4 a) {
    __nv_bfloat162 p0 = __floats2bfloat162_rn(a.x, a.y);
    __nv_bfloat162 p1 = __floats2bfloat162_rn(a.z, a.w);
    uint2 w;
    w.x = *reinterpret_cast<unsigned int*>(&p0);
    w.y = *reinterpret_cast<unsigned int*>(&p1);
    return w;
}

// ---------------------------------------------------------------------------
// Fused kernel: normalization + batched GEMM sim = A @ B^T.
// Reads RAW fp32 inputs, converts to bf16 while staging to smem, accumulates
// per-row sum-of-squares during loads (free), applies 1/(|x||y|) in epilogue.
// Grid (2,2,B), 128x128 tile per CTA, 256 thr (8 warps: 2 M x 4 N), warp tile
// 64x32, K-tile 32, double-buffered smem pad-40, ldmatrix fragments.
// Epilogue: dist = 1 - clamp(sim) stored ROW-MAJOR as float2.
// ---------------------------------------------------------------------------
#define KT 32
#define LDP 40

__global__ __launch_bounds__(256, 2) void gemm_kernel(const float* __restrict__ s1,
                                                      const float* __restrict__ s2) {
    __shared__ __nv_bfloat16 As[2][128 * LDP];
    __shared__ __nv_bfloat16 Bs[2][128 * LDP];
    __shared__ float invA_s[128];
    __shared__ float invB_s[128];

    int b  = blockIdx.z;
    int i0 = blockIdx.x * 128;
    int j0 = blockIdx.y * 128;
    int t    = threadIdx.x;
    int lane = t & 31;
    int w    = t >> 5;
    int wm = w & 1;
    int wn = w >> 1;
    int gid = lane >> 2;
    int tig = lane & 3;

    const float* Ag = s1 + (size_t)b * NN * DD + (size_t)i0 * DD;
    const float* Bg = s2 + (size_t)b * MM * DD + (size_t)j0 * DD;

    int lr = t >> 3;        // 0..31 (row within 32-row group)
    int lc = (t & 7) * 4;   // k-col 0,4,...,28

    float acc[4][4][4];
#pragma unroll
    for (int mt = 0; mt < 4; mt++)
#pragma unroll
        for (int nt = 0; nt < 4; nt++)
#pragma unroll
            for (int c = 0; c < 4; c++) acc[mt][nt][c] = 0.f;

    float ssA[4] = {0.f, 0.f, 0.f, 0.f};
    float ssB[4] = {0.f, 0.f, 0.f, 0.f};

    uint2 ra[4], rb[4];
#pragma unroll
    for (int r4 = 0; r4 < 4; r4++) {
        float4 a4 = *(const float4*)(Ag + (size_t)(lr + r4 * 32) * DD + lc);
        float4 b4 = *(const float4*)(Bg + (size_t)(lr + r4 * 32) * DD + lc);
        ssA[r4] += a4.x * a4.x + a4.y * a4.y + a4.z * a4.z + a4.w * a4.w;
        ssB[r4] += b4.x * b4.x + b4.y * b4.y + b4.z * b4.z + b4.w * b4.w;
        ra[r4] = cvt_f4_bf16(a4);
        rb[r4] = cvt_f4_bf16(b4);
    }
    int buf = 0;
#pragma unroll
    for (int r4 = 0; r4 < 4; r4++) {
        *(uint2*)&As[buf][(lr + r4 * 32) * LDP + lc] = ra[r4];
        *(uint2*)&Bs[buf][(lr + r4 * 32) * LDP + lc] = rb[r4];
    }
    __syncthreads();

    // ldmatrix lane address components
    int a_row_in = (lane & 15);
    int a_koff   = (lane >> 4) * 8;
    int b_row_in = ((lane >> 4) << 3) + (lane & 7);
    int b_koff   = ((lane >> 3) & 1) * 8;

    for (int kt = 0; kt < DD / KT; kt++) {
        int nk = kt + 1;
        if (nk < DD / KT) {
#pragma unroll
            for (int r4 = 0; r4 < 4; r4++) {
                float4 a4 = *(const float4*)(Ag + (size_t)(lr + r4 * 32) * DD + nk * KT + lc);
                float4 b4 = *(const float4*)(Bg + (size_t)(lr + r4 * 32) * DD + nk * KT + lc);
                ssA[r4] += a4.x * a4.x + a4.y * a4.y + a4.z * a4.z + a4.w * a4.w;
                ssB[r4] += b4.x * b4.x + b4.y * b4.y + b4.z * b4.z + b4.w * b4.w;
                ra[r4] = cvt_f4_bf16(a4);
                rb[r4] = cvt_f4_bf16(b4);
            }
        }
#pragma unroll
        for (int kk = 0; kk < KT; kk += 16) {
            uint32_t af[4][4];
            uint32_t bf2[2][4];
#pragma unroll
            for (int mt = 0; mt < 4; mt++) {
                int arow = wm * 64 + mt * 16 + a_row_in;
                uint32_t addr = smem_u32(&As[buf][arow * LDP + kk + a_koff]);
                ldsm_x4(af[mt][0], af[mt][1], af[mt][2], af[mt][3], addr);
            }
#pragma unroll
            for (int ntp = 0; ntp < 2; ntp++) {
                int brow = wn * 32 + ntp * 16 + b_row_in;
                uint32_t addr = smem_u32(&Bs[buf][brow * LDP + kk + b_koff]);
                ldsm_x4(bf2[ntp][0], bf2[ntp][1], bf2[ntp][2], bf2[ntp][3], addr);
            }
#pragma unroll
            for (int mt = 0; mt < 4; mt++)
#pragma unroll
                for (int nt = 0; nt < 4; nt++) {
                    uint32_t b0 = bf2[nt >> 1][(nt & 1) * 2];
                    uint32_t b1 = bf2[nt >> 1][(nt & 1) * 2 + 1];
                    asm volatile(
                        "mma.sync.aligned.m16n8k16.row.col.f32.bf16.bf16.f32 "
                        "{%0,%1,%2,%3}, {%4,%5,%6,%7}, {%8,%9}, {%0,%1,%2,%3};\n"
                        : "+f"(acc[mt][nt][0]), "+f"(acc[mt][nt][1]),
                          "+f"(acc[mt][nt][2]), "+f"(acc[mt][nt][3])
                        : "r"(af[mt][0]), "r"(af[mt][1]), "r"(af[mt][2]), "r"(af[mt][3]),
                          "r"(b0), "r"(b1));
                }
        }
        if (nk < DD / KT) {
            int nbuf = buf ^ 1;
#pragma unroll
            for (int r4 = 0; r4 < 4; r4++) {
                *(uint2*)&As[nbuf][(lr + r4 * 32) * LDP + lc] = ra[r4];
                *(uint2*)&Bs[nbuf][(lr + r4 * 32) * LDP + lc] = rb[r4];
            }
        }
        __syncthreads();
        buf ^= 1;
    }

    // Per-row inverse norms: 8 threads (consecutive lanes) share each row.
#pragma unroll
    for (int r4 = 0; r4 < 4; r4++) {
#pragma unroll
        for (int o = 1; o < 8; o <<= 1) {
            ssA[r4] += __shfl_xor_sync(0xffffffffu, ssA[r4], o);
            ssB[r4] += __shfl_xor_sync(0xffffffffu, ssB[r4], o);
        }
        if ((lane & 7) == 0) {
            int row = lr + r4 * 32;
            invA_s[row] = 1.0f / fmaxf(sqrtf(ssA[r4]), 1e-12f);
            invB_s[row] = 1.0f / fmaxf(sqrtf(ssB[r4]), 1e-12f);
        }
    }
    __syncthreads();

    // Epilogue: sim = acc * invA[i] * invB[j]; dist = 1 - clamp(sim).
    float* dT = g_dist + (size_t)b * 65536;
#pragma unroll
    for (int mt = 0; mt < 4; mt++) {
#pragma unroll
        for (int nt = 0; nt < 4; nt++) {
            int li = wm * 64 + mt * 16 + gid;
            int lj = wn * 32 + nt * 8 + tig * 2;
            float ia0 = invA_s[li];
            float ia1 = invA_s[li + 8];
            float ib0 = invB_s[lj];
            float ib1 = invB_s[lj + 1];
            float2 v0, v1;
            v0.x = 1.0f - fminf(fmaxf(acc[mt][nt][0] * ia0 * ib0, -1.f), 1.f);
            v0.y = 1.0f - fminf(fmaxf(acc[mt][nt][1] * ia0 * ib1, -1.f), 1.f);
            v1.x = 1.0f - fminf(fmaxf(acc[mt][nt][2] * ia1 * ib0, -1.f), 1.f);
            v1.y = 1.0f - fminf(fmaxf(acc[mt][nt][3] * ia1 * ib1, -1.f), 1.f);
            int i = i0 + li;
            int j = j0 + lj;
            *(float2*)&dT[(size_t)i * 256 + j]       = v0;
            *(float2*)&dT[(size_t)(i + 8) * 256 + j] = v1;
        }
    }
}

// ---------------------------------------------------------------------------
// Kernel 2: banded DTW, row-streaming min-plus scan. One warp per batch; lane
// owns 8 columns. Rows prefetched via cp.async ring.
// ---------------------------------------------------------------------------
#define SDEPTH 8

__global__ __launch_bounds__(128) void dtw_kernel(float* __restrict__ out) {
    __shared__ float ring[4][SDEPTH][256];
    int w     = threadIdx.x >> 5;
    int lane  = threadIdx.x & 31;
    int batch = blockIdx.x * 4 + w;
    const float* E = g_dist + (size_t)batch * 65536;
    int cbase = lane * 8;

    for (int s = 0; s < SDEPTH; s++) {
        uint32_t sa = smem_u32(&ring[w][s][cbase]);
        const float* src = E + (size_t)s * 256 + cbase;
        cp16(sa, src);
        cp16(sa + 16, src + 4);
        asm volatile("cp.async.commit_group;\n" ::: "memory");
    }

    float prev[8];

    for (int r = 0; r < 256; r++) {
        asm volatile("cp.async.wait_group 7;\n" ::: "memory");
        float e[8];
        const float* slot = &ring[w][r & (SDEPTH - 1)][cbase];
#pragma unroll
        for (int u = 0; u < 8; u++) e[u] = slot[u];

        int nr = r + SDEPTH;
        if (nr < 256) {
            uint32_t sa = smem_u32(&ring[w][nr & (SDEPTH - 1)][cbase]);
            const float* src = E + (size_t)nr * 256 + cbase;
            cp16(sa, src);
            cp16(sa + 16, src + 4);
        }
        asm volatile("cp.async.commit_group;\n" ::: "memory");

        if (r == 0) {
            float ps[8];
            float run = 0.f;
#pragma unroll
            for (int u = 0; u < 8; u++) { run += e[u]; ps[u] = run; }
            float acc = run;
#pragma unroll
            for (int d = 1; d < 32; d <<= 1) {
                float p = __shfl_up_sync(0xffffffffu, acc, d);
                if (lane >= d) acc += p;
            }
            float excl = acc - run;
#pragma unroll
            for (int u = 0; u < 8; u++) {
                float tv = excl + ps[u];
                prev[u] = (cbase + u <= RBAND) ? tv : BIGF;
            }
        } else {
            float pl = __shfl_up_sync(0xffffffffu, prev[7], 1);
            if (lane == 0) pl = BIGF;
            float bb[8], ss[8];
#pragma unroll
            for (int u = 0; u < 8; u++) {
                int c = cbase + u;
                float pjm1 = u ? prev[u - 1] : pl;
                bool ib = (c >= 1) && (c >= r - RBAND) && (c <= r + RBAND);
                bb[u] = ib ? fminf(prev[u], pjm1) + e[u] : BIGF;
                ss[u] = ib ? e[u] : BIGF;
            }
            if (lane == 0) {
                bb[0] = (r <= RBAND) ? prev[0] + e[0] : BIGF;
                ss[0] = BIGF;
            }
            float tl[8], P[8];
            tl[0] = bb[0];
            P[0]  = ss[0];
#pragma unroll
            for (int u = 1; u < 8; u++) {
                tl[u] = fminf(bb[u], tl[u - 1] + ss[u]);
                P[u]  = P[u - 1] + ss[u];
            }
            float S = P[7], T = tl[7];
#pragma unroll
            for (int d = 1; d < 32; d <<= 1) {
                float Sp = __shfl_up_sync(0xffffffffu, S, d);
                float Tp = __shfl_up_sync(0xffffffffu, T, d);
                if (lane >= d) {
                    T = fminf(T, Tp + S);
                    S = S + Sp;
                }
            }
            float cin = __shfl_up_sync(0xffffffffu, T, 1);
            if (lane == 0) cin = BIGF;
#pragma unroll
            for (int u = 0; u < 8; u++) prev[u] = fminf(tl[u], cin + P[u]);
        }
    }

    if (lane == 31) out[batch] = prev[7];
}

// ---------------------------------------------------------------------------
extern "C" void kernel_launch(void* const* d_in, const int* in_sizes, int n_in,
                              void* d_out, int out_size) {
    const float* s1 = (const float*)d_in[0];
    const float* s2 = (const float*)d_in[1];
    float* out = (float*)d_out;

    dim3 g(2, 2, BB);
    gemm_kernel<<<g, 256>>>(s1, s2);

    dtw_kernel<<<64, 128>>>(out);
}